// round 6
// baseline (speedup 1.0000x reference)
#include <cuda_runtime.h>
#include <cuda_bf16.h>
#include <cstdint>

#define HNUM 8
#define NSEQ 4096
#define FIN  512
#define HD   64

// ---------------- scratch (static device globals; no allocations) ----------
__device__ uint32_t g_WH[3 * HNUM * HD * (FIN / 2)];
__device__ uint32_t g_WL[3 * HNUM * HD * (FIN / 2)];
__device__ uint32_t g_WOH[FIN * (FIN / 2)];
__device__ uint32_t g_WOL[FIN * (FIN / 2)];
__device__ uint32_t g_QH[HNUM * NSEQ * (HD / 2)];
__device__ uint32_t g_QL[HNUM * NSEQ * (HD / 2)];
__device__ uint32_t g_KH[HNUM * NSEQ * (HD / 2)];
__device__ uint32_t g_KL[HNUM * NSEQ * (HD / 2)];
__device__ unsigned short g_VTH[HNUM * HD * NSEQ];
__device__ unsigned short g_VTL[HNUM * HD * NSEQ];
__device__ uint32_t g_HH[NSEQ * (FIN / 2)];
__device__ uint32_t g_HL[NSEQ * (FIN / 2)];

// ---------------- helpers --------------------------------------------------
__device__ __forceinline__ uint32_t pack_bf16x2(float lo_elem, float hi_elem) {
    return (uint32_t)__bfloat16_as_ushort(__float2bfloat16_rn(lo_elem)) |
           ((uint32_t)__bfloat16_as_ushort(__float2bfloat16_rn(hi_elem)) << 16);
}

__device__ __forceinline__ void split2(float a, float b, uint32_t& hi, uint32_t& lo) {
    float ah = __bfloat162float(__float2bfloat16_rn(a));
    float bh = __bfloat162float(__float2bfloat16_rn(b));
    hi = pack_bf16x2(a, b);
    lo = pack_bf16x2(a - ah, b - bh);
}

__device__ __forceinline__ void mma16816(float* c,
                                         uint32_t a0, uint32_t a1, uint32_t a2, uint32_t a3,
                                         uint32_t b0, uint32_t b1) {
    asm volatile(
        "mma.sync.aligned.m16n8k16.row.col.f32.bf16.bf16.f32 "
        "{%0,%1,%2,%3},{%4,%5,%6,%7},{%8,%9},{%0,%1,%2,%3};\n"
        : "+f"(c[0]), "+f"(c[1]), "+f"(c[2]), "+f"(c[3])
        : "r"(a0), "r"(a1), "r"(a2), "r"(a3), "r"(b0), "r"(b1));
}

__device__ __forceinline__ void ldsm4(uint32_t& r0, uint32_t& r1, uint32_t& r2,
                                      uint32_t& r3, uint32_t addr) {
    asm volatile("ldmatrix.sync.aligned.m8n8.x4.shared.b16 {%0,%1,%2,%3},[%4];"
                 : "=r"(r0), "=r"(r1), "=r"(r2), "=r"(r3) : "r"(addr));
}

__device__ __forceinline__ void cp16(uint32_t dst, const void* src) {
    asm volatile("cp.async.cg.shared.global [%0], [%1], 16;" :: "r"(dst), "l"(src));
}
__device__ __forceinline__ void cp_commit() {
    asm volatile("cp.async.commit_group;" ::: "memory");
}
__device__ __forceinline__ void cp_wait1() {
    asm volatile("cp.async.wait_group 1;" ::: "memory");
}
__device__ __forceinline__ void cp_wait0() {
    asm volatile("cp.async.wait_group 0;" ::: "memory");
}
__device__ __forceinline__ void prefetchL2(const void* p) {
    asm volatile("prefetch.global.L2 [%0];" :: "l"(p));
}

#define NEG_BIG (-1.0e30f)
#define SCALE2  0.18033688f   /* 0.125 * log2(e) */

// ---------------- split kernel: fp32 -> packed bf16 hi/lo (weights) ---------
__global__ void __launch_bounds__(256) split_kernel(const float* __restrict__ src,
                                                    int which, int nquads) {
    uint32_t* dH;
    uint32_t* dL;
    switch (which) {
        case 1: dH = g_WH;          dL = g_WL;          break;
        case 2: dH = g_WH + 131072; dL = g_WL + 131072; break;
        case 3: dH = g_WH + 262144; dL = g_WL + 262144; break;
        default: dH = g_WOH;        dL = g_WOL;         break;
    }
    for (int i = blockIdx.x * blockDim.x + threadIdx.x; i < nquads;
         i += gridDim.x * blockDim.x) {
        float4 v = reinterpret_cast<const float4*>(src)[i];
        uint32_t h0, l0, h1, l1;
        split2(v.x, v.y, h0, l0);
        split2(v.z, v.w, h1, l1);
        reinterpret_cast<uint2*>(dH)[i] = make_uint2(h0, h1);
        reinterpret_cast<uint2*>(dL)[i] = make_uint2(l0, l1);
    }
}

// ---------------- stage 1: fused QKV projection -----------------------------
#define QKV_SMEM_WORDS 18432

__global__ void __launch_bounds__(128, 3) qkv_fused(const float* __restrict__ X) {
    extern __shared__ __align__(16) uint32_t qs[];
    const uint32_t sbase = (uint32_t)__cvta_generic_to_shared(qs);
    const int tid = threadIdx.x, wid = tid >> 5, lane = tid & 31;
    const int g = lane >> 2, q = lane & 3;
    const int bm = blockIdx.x, h = blockIdx.y;

    const int jm = lane >> 3, im = lane & 7;
    const uint32_t lwB = (uint32_t)(((8 * (jm >> 1) + im) * 36 + (jm & 1) * 4) * 4);
    const uint32_t lwA = (uint32_t)(((lane & 15) * 36 + (lane >> 4) * 4) * 4);

    float acc[3][8][4];
#pragma unroll
    for (int z = 0; z < 3; z++)
#pragma unroll
        for (int i = 0; i < 8; i++)
#pragma unroll
            for (int j = 0; j < 4; j++) acc[z][i][j] = 0.f;

    const float* Xbase = X + ((size_t)h * NSEQ + (size_t)bm * 64) * FIN;

    for (int kc = 0; kc < 8; kc++) {
#pragma unroll
        for (int j = 0; j < 8; j++) {
            int idx = tid + j * 128;
            int r = idx >> 4, c4 = (idx & 15) << 2;
            float4 v = *reinterpret_cast<const float4*>(Xbase + (size_t)r * FIN + kc * 64 + c4);
            uint32_t h0, l0, h1, l1;
            split2(v.x, v.y, h0, l0);
            split2(v.z, v.w, h1, l1);
            *reinterpret_cast<uint2*>(&qs[r * 36 + (c4 >> 1)]) = make_uint2(h0, h1);
            *reinterpret_cast<uint2*>(&qs[2304 + r * 36 + (c4 >> 1)]) = make_uint2(l0, l1);
        }
#pragma unroll
        for (int z = 0; z < 3; z++) {
            const uint32_t* BH = g_WH + ((size_t)(z * HNUM + h) * HD) * 256 + kc * 32;
            const uint32_t* BL = g_WL + ((size_t)(z * HNUM + h) * HD) * 256 + kc * 32;
#pragma unroll
            for (int j = 0; j < 4; j++) {
                int idx = tid + j * 128;
                int r = idx >> 3, c = (idx & 7) << 2;
                *reinterpret_cast<uint4*>(&qs[4608 + z * 2304 + r * 36 + c]) =
                    *reinterpret_cast<const uint4*>(BH + (size_t)r * 256 + c);
                *reinterpret_cast<uint4*>(&qs[11520 + z * 2304 + r * 36 + c]) =
                    *reinterpret_cast<const uint4*>(BL + (size_t)r * 256 + c);
            }
        }
        __syncthreads();
#pragma unroll
        for (int ks = 0; ks < 4; ks++) {
            uint32_t a0h, a1h, a2h, a3h, a0l, a1l, a2l, a3l;
            uint32_t aoff = sbase + (uint32_t)((wid * 16 * 36 + ks * 8) * 4) + lwA;
            ldsm4(a0h, a1h, a2h, a3h, aoff);
            ldsm4(a0l, a1l, a2l, a3l, aoff + 2304 * 4);
#pragma unroll
            for (int z = 0; z < 3; z++) {
                uint32_t bbase = sbase + (uint32_t)((4608 + z * 2304) * 4);
#pragma unroll
                for (int p = 0; p < 4; p++) {
                    uint32_t off = bbase + (uint32_t)((p * 576 + ks * 8) * 4) + lwB;
                    uint32_t b0, b1, b2, b3, c0, c1, c2, c3;
                    ldsm4(b0, b1, b2, b3, off);
                    ldsm4(c0, c1, c2, c3, off + 6912 * 4);
                    mma16816(acc[z][2 * p],     a0h, a1h, a2h, a3h, b0, b1);
                    mma16816(acc[z][2 * p],     a0h, a1h, a2h, a3h, c0, c1);
                    mma16816(acc[z][2 * p],     a0l, a1l, a2l, a3l, b0, b1);
                    mma16816(acc[z][2 * p + 1], a0h, a1h, a2h, a3h, b2, b3);
                    mma16816(acc[z][2 * p + 1], a0h, a1h, a2h, a3h, c2, c3);
                    mma16816(acc[z][2 * p + 1], a0l, a1l, a2l, a3l, b2, b3);
                }
            }
        }
        __syncthreads();
    }

    const int r0 = wid * 16 + g;
#pragma unroll
    for (int z = 0; z < 2; z++) {
        uint32_t* dH = (z == 0) ? g_QH : g_KH;
        uint32_t* dL = (z == 0) ? g_QL : g_KL;
        const size_t rb0 = (size_t)(h * NSEQ + bm * 64 + r0) * 32;
        const size_t rb1 = rb0 + 8 * 32;
#pragma unroll
        for (int nt = 0; nt < 8; nt++) {
            int w = nt * 4 + q;
            uint32_t H, L;
            split2(acc[z][nt][0], acc[z][nt][1], H, L);
            dH[rb0 + w] = H; dL[rb0 + w] = L;
            split2(acc[z][nt][2], acc[z][nt][3], H, L);
            dH[rb1 + w] = H; dL[rb1 + w] = L;
        }
    }
    {
        const int n0 = bm * 64 + r0;
#pragma unroll
        for (int nt = 0; nt < 8; nt++) {
            int cx = nt * 8 + 2 * q;
#pragma unroll
            for (int e = 0; e < 2; e++) {
                size_t b0 = (size_t)(h * HD + cx + e) * NSEQ;
                float v0 = acc[2][nt][e], v1 = acc[2][nt][2 + e];
                float h0 = __bfloat162float(__float2bfloat16_rn(v0));
                float h1 = __bfloat162float(__float2bfloat16_rn(v1));
                g_VTH[b0 + n0]     = __bfloat16_as_ushort(__float2bfloat16_rn(v0));
                g_VTL[b0 + n0]     = __bfloat16_as_ushort(__float2bfloat16_rn(v0 - h0));
                g_VTH[b0 + n0 + 8] = __bfloat16_as_ushort(__float2bfloat16_rn(v1));
                g_VTL[b0 + n0 + 8] = __bfloat16_as_ushort(__float2bfloat16_rn(v1 - h1));
            }
        }
    }
}

// ---------------- stage 3: output projection ------------------------------
__device__ __forceinline__ void gemm_accum(const uint32_t* __restrict__ AHg,
                                           const uint32_t* __restrict__ ALg,
                                           const uint32_t* __restrict__ BHg,
                                           const uint32_t* __restrict__ BLg,
                                           float acc[8][4]) {
    __shared__ __align__(16) uint32_t AsH[128][36];
    __shared__ __align__(16) uint32_t AsL[128][36];
    __shared__ __align__(16) uint32_t BsH[64][36];
    __shared__ __align__(16) uint32_t BsL[64][36];

    const int tid = threadIdx.x;
    const int wid = tid >> 5, lane = tid & 31;
    const int g = lane >> 2, q = lane & 3;

    for (int kc = 0; kc < 256; kc += 32) {
#pragma unroll
        for (int j = 0; j < 4; j++) {
            int idx = tid + j * 256;
            int r = idx >> 3, c = (idx & 7) << 2;
            *reinterpret_cast<uint4*>(&AsH[r][c]) =
                *reinterpret_cast<const uint4*>(AHg + (size_t)r * 256 + kc + c);
            *reinterpret_cast<uint4*>(&AsL[r][c]) =
                *reinterpret_cast<const uint4*>(ALg + (size_t)r * 256 + kc + c);
        }
#pragma unroll
        for (int j = 0; j < 2; j++) {
            int idx = tid + j * 256;
            int r = idx >> 3, c = (idx & 7) << 2;
            *reinterpret_cast<uint4*>(&BsH[r][c]) =
                *reinterpret_cast<const uint4*>(BHg + (size_t)r * 256 + kc + c);
            *reinterpret_cast<uint4*>(&BsL[r][c]) =
                *reinterpret_cast<const uint4*>(BLg + (size_t)r * 256 + kc + c);
        }
        __syncthreads();
#pragma unroll
        for (int ks = 0; ks < 4; ks++) {
            const int ar = wid * 16 + g;
            const int wi = ks * 8 + q;
            uint32_t a0h = AsH[ar][wi],     a1h = AsH[ar + 8][wi];
            uint32_t a2h = AsH[ar][wi + 4], a3h = AsH[ar + 8][wi + 4];
            uint32_t a0l = AsL[ar][wi],     a1l = AsL[ar + 8][wi];
            uint32_t a2l = AsL[ar][wi + 4], a3l = AsL[ar + 8][wi + 4];
#pragma unroll
            for (int nt = 0; nt < 8; nt++) {
                const int br = nt * 8 + g;
                uint32_t b0h = BsH[br][wi], b1h = BsH[br][wi + 4];
                uint32_t b0l = BsL[br][wi], b1l = BsL[br][wi + 4];
                mma16816(acc[nt], a0h, a1h, a2h, a3h, b0h, b1h);
                mma16816(acc[nt], a0h, a1h, a2h, a3h, b0l, b1l);
                mma16816(acc[nt], a0l, a1l, a2l, a3l, b0h, b1h);
            }
        }
        __syncthreads();
    }
}

__global__ void __launch_bounds__(256) out_kernel(float* __restrict__ out) {
    const int bm = blockIdx.x, bn = blockIdx.y;
    const int tid = threadIdx.x;
    const int wid = tid >> 5, lane = tid & 31;
    const int g = lane >> 2, q = lane & 3;

    float acc[8][4];
#pragma unroll
    for (int i = 0; i < 8; i++)
#pragma unroll
        for (int j = 0; j < 4; j++) acc[i][j] = 0.f;

    gemm_accum(g_HH + (size_t)bm * 128 * 256, g_HL + (size_t)bm * 128 * 256,
               g_WOH + (size_t)bn * HD * 256, g_WOL + (size_t)bn * HD * 256, acc);

    const int r0 = wid * 16 + g;
#pragma unroll
    for (int nt = 0; nt < 8; nt++) {
        int cx = bn * HD + nt * 8 + 2 * q;
        *reinterpret_cast<float2*>(out + (size_t)(bm * 128 + r0) * FIN + cx) =
            make_float2(acc[nt][0], acc[nt][1]);
        *reinterpret_cast<float2*>(out + (size_t)(bm * 128 + r0 + 8) * FIN + cx) =
            make_float2(acc[nt][2], acc[nt][3]);
    }
}

// ---------------- stage 2: flash attention (BM=128, 128 threads, 32 rows/warp)
#define ATTN_BUF_WORDS 9216
#define ATTN_SMEM_BYTES (2 * ATTN_BUF_WORDS * 4)

__device__ __forceinline__ void issue_tile(int h, int nb, uint32_t sbase) {
    const int tid = threadIdx.x;
#pragma unroll
    for (int j = 0; j < 4; j++) {
        int chunk = tid + j * 128;
        int r = chunk >> 3, c = chunk & 7;
        const uint32_t* sKH = g_KH + (size_t)(h * NSEQ + nb * 64 + r) * 32 + c * 4;
        const uint32_t* sKL = g_KL + (size_t)(h * NSEQ + nb * 64 + r) * 32 + c * 4;
        const unsigned short* sVH = g_VTH + (size_t)(h * HD + r) * NSEQ + nb * 64 + c * 8;
        const unsigned short* sVL = g_VTL + (size_t)(h * HD + r) * NSEQ + nb * 64 + c * 8;
        uint32_t off = (uint32_t)(r * 36 + c * 4) * 4;
        cp16(sbase + off, sKH);
        cp16(sbase + off + 2304 * 4, sKL);
        cp16(sbase + off + 4608 * 4, sVH);
        cp16(sbase + off + 6912 * 4, sVL);
    }
}

__global__ void __launch_bounds__(128) attn_kernel(const int* __restrict__ mask) {
    extern __shared__ __align__(16) uint32_t sm[];
    const uint32_t smem_u32 = (uint32_t)__cvta_generic_to_shared(sm);

    const int tid = threadIdx.x, wid = tid >> 5, lane = tid & 31;
    const int g = lane >> 2, q = lane & 3;
    const int bm = blockIdx.x, h = blockIdx.y;

    const int jm = lane >> 3, im = lane & 7;
    const uint32_t lwB = (uint32_t)(((8 * (jm >> 1) + im) * 36 + (jm & 1) * 4) * 4);

    // ---- Q fragments: warp owns rows bm*128 + wid*32 + grp*16 + {g, g+8}
    uint32_t qh[4][2][4], ql[4][2][4];
#pragma unroll
    for (int grp = 0; grp < 2; grp++) {
        const size_t rb0 = (size_t)(h * NSEQ + bm * 128 + wid * 32 + grp * 16 + g) * 32;
        const size_t rb1 = rb0 + 8 * 32;
#pragma unroll
        for (int ks = 0; ks < 4; ks++) {
            int wi = ks * 8 + q;
            qh[ks][grp][0] = g_QH[rb0 + wi];
            qh[ks][grp][1] = g_QH[rb1 + wi];
            qh[ks][grp][2] = g_QH[rb0 + wi + 4];
            qh[ks][grp][3] = g_QH[rb1 + wi + 4];
            ql[ks][grp][0] = g_QL[rb0 + wi];
            ql[ks][grp][1] = g_QL[rb1 + wi];
            ql[ks][grp][2] = g_QL[rb0 + wi + 4];
            ql[ks][grp][3] = g_QL[rb1 + wi + 4];
        }
    }

    const int* mr[2][2];
#pragma unroll
    for (int grp = 0; grp < 2; grp++) {
        mr[grp][0] = mask +
            ((size_t)h * NSEQ + (size_t)(bm * 128 + wid * 32 + grp * 16 + g)) * NSEQ;
        mr[grp][1] = mr[grp][0] + 8 * NSEQ;
    }

    float O[2][8][4];
#pragma unroll
    for (int grp = 0; grp < 2; grp++)
#pragma unroll
        for (int i = 0; i < 8; i++)
#pragma unroll
            for (int j = 0; j < 4; j++) O[grp][i][j] = 0.f;
    const float NEGINF = __int_as_float(0xff800000);
    float m0[2] = {NEGINF, NEGINF}, m1[2] = {NEGINF, NEGINF};
    float l0s[2] = {0.f, 0.f}, l1s[2] = {0.f, 0.f};

#pragma unroll
    for (int grp = 0; grp < 2; grp++) {
        prefetchL2(mr[grp][0]);
        prefetchL2(mr[grp][0] + 32);
        prefetchL2(mr[grp][1]);
        prefetchL2(mr[grp][1] + 32);
    }

    issue_tile(h, 0, smem_u32);
    cp_commit();

    for (int nb = 0; nb < NSEQ / 64; nb++) {
        if (nb + 1 < NSEQ / 64) {
#pragma unroll
            for (int grp = 0; grp < 2; grp++) {
                const int* p0 = mr[grp][0] + (nb + 1) * 64;
                const int* p1 = mr[grp][1] + (nb + 1) * 64;
                prefetchL2(p0);
                prefetchL2(p0 + 32);
                prefetchL2(p1);
                prefetchL2(p1 + 32);
            }
        }

        __syncthreads();
        if (nb + 1 < NSEQ / 64) {
            issue_tile(h, nb + 1, smem_u32 + ((nb + 1) & 1) * ATTN_BUF_WORDS * 4);
            cp_commit();
            cp_wait1();
        } else {
            cp_wait0();
        }
        __syncthreads();

        const uint32_t kaddr  = smem_u32 + (uint32_t)((nb & 1) * ATTN_BUF_WORDS) * 4;
        const uint32_t kaddrL = kaddr + 2304 * 4;
        const uint32_t vaddr  = kaddr + 4608 * 4;
        const uint32_t vaddrL = kaddr + 6912 * 4;

        // ---- S = Q * K^T  (each K fragment pair feeds both row groups)
        float S[2][8][4];
#pragma unroll
        for (int grp = 0; grp < 2; grp++)
#pragma unroll
            for (int i = 0; i < 8; i++)
#pragma unroll
                for (int j = 0; j < 4; j++) S[grp][i][j] = 0.f;
#pragma unroll
        for (int ks = 0; ks < 4; ks++) {
#pragma unroll
            for (int p = 0; p < 4; p++) {
                uint32_t off = (uint32_t)((p * 576 + ks * 8) * 4) + lwB;
                uint32_t h0, h1, h2, h3, l0, l1, l2, l3;
                ldsm4(h0, h1, h2, h3, kaddr + off);
                ldsm4(l0, l1, l2, l3, kaddrL + off);
#pragma unroll
                for (int grp = 0; grp < 2; grp++) {
                    mma16816(S[grp][2 * p], qh[ks][grp][0], qh[ks][grp][1],
                             qh[ks][grp][2], qh[ks][grp][3], h0, h1);
                    mma16816(S[grp][2 * p], qh[ks][grp][0], qh[ks][grp][1],
                             qh[ks][grp][2], qh[ks][grp][3], l0, l1);
                    mma16816(S[grp][2 * p], ql[ks][grp][0], ql[ks][grp][1],
                             ql[ks][grp][2], ql[ks][grp][3], h0, h1);
                    mma16816(S[grp][2 * p + 1], qh[ks][grp][0], qh[ks][grp][1],
                             qh[ks][grp][2], qh[ks][grp][3], h2, h3);
                    mma16816(S[grp][2 * p + 1], qh[ks][grp][0], qh[ks][grp][1],
                             qh[ks][grp][2], qh[ks][grp][3], l2, l3);
                    mma16816(S[grp][2 * p + 1], ql[ks][grp][0], ql[ks][grp][1],
                             ql[ks][grp][2], ql[ks][grp][3], h2, h3);
                }
            }
        }

        // ---- mask + scale + online softmax per row group
#pragma unroll
        for (int grp = 0; grp < 2; grp++) {
#pragma unroll
            for (int nt = 0; nt < 8; nt++) {
                int2 ma = *reinterpret_cast<const int2*>(mr[grp][0] + nb * 64 + nt * 8 + 2 * q);
                int2 mb = *reinterpret_cast<const int2*>(mr[grp][1] + nb * 64 + nt * 8 + 2 * q);
                S[grp][nt][0] = ma.x ? S[grp][nt][0] * SCALE2 : NEG_BIG;
                S[grp][nt][1] = ma.y ? S[grp][nt][1] * SCALE2 : NEG_BIG;
                S[grp][nt][2] = mb.x ? S[grp][nt][2] * SCALE2 : NEG_BIG;
                S[grp][nt][3] = mb.y ? S[grp][nt][3] * SCALE2 : NEG_BIG;
            }
        }

        float al0[2], al1[2];
#pragma unroll
        for (int grp = 0; grp < 2; grp++) {
            float mx0 = S[grp][0][0], mx1 = S[grp][0][2];
#pragma unroll
            for (int nt = 0; nt < 8; nt++) {
                mx0 = fmaxf(mx0, fmaxf(S[grp][nt][0], S[grp][nt][1]));
                mx1 = fmaxf(mx1, fmaxf(S[grp][nt][2], S[grp][nt][3]));
            }
            mx0 = fmaxf(mx0, __shfl_xor_sync(0xffffffffu, mx0, 1));
            mx0 = fmaxf(mx0, __shfl_xor_sync(0xffffffffu, mx0, 2));
            mx1 = fmaxf(mx1, __shfl_xor_sync(0xffffffffu, mx1, 1));
            mx1 = fmaxf(mx1, __shfl_xor_sync(0xffffffffu, mx1, 2));

            float mn0 = fmaxf(m0[grp], mx0), mn1 = fmaxf(m1[grp], mx1);
            al0[grp] = exp2f(m0[grp] - mn0);
            al1[grp] = exp2f(m1[grp] - mn1);
            m0[grp] = mn0;
            m1[grp] = mn1;

            float rs0 = 0.f, rs1 = 0.f;
#pragma unroll
            for (int nt = 0; nt < 8; nt++) {
                S[grp][nt][0] = exp2f(S[grp][nt][0] - mn0);
                S[grp][nt][1] = exp2f(S[grp][nt][1] - mn0);
                S[grp][nt][2] = exp2f(S[grp][nt][2] - mn1);
                S[grp][nt][3] = exp2f(S[grp][nt][3] - mn1);
                rs0 += S[grp][nt][0] + S[grp][nt][1];
                rs1 += S[grp][nt][2] + S[grp][nt][3];
            }
            rs0 += __shfl_xor_sync(0xffffffffu, rs0, 1);
            rs0 += __shfl_xor_sync(0xffffffffu, rs0, 2);
            rs1 += __shfl_xor_sync(0xffffffffu, rs1, 1);
            rs1 += __shfl_xor_sync(0xffffffffu, rs1, 2);
            l0s[grp] = l0s[grp] * al0[grp] + rs0;
            l1s[grp] = l1s[grp] * al1[grp] + rs1;
#pragma unroll
            for (int nt = 0; nt < 8; nt++) {
                O[grp][nt][0] *= al0[grp];
                O[grp][nt][1] *= al0[grp];
                O[grp][nt][2] *= al1[grp];
                O[grp][nt][3] *= al1[grp];
            }
        }

        // ---- O += P * V  (each V fragment pair feeds both row groups)
#pragma unroll
        for (int ks = 0; ks < 4; ks++) {
            uint32_t ah[2][4], al[2][4];
#pragma unroll
            for (int grp = 0; grp < 2; grp++) {
                split2(S[grp][2 * ks][0],     S[grp][2 * ks][1],     ah[grp][0], al[grp][0]);
                split2(S[grp][2 * ks][2],     S[grp][2 * ks][3],     ah[grp][1], al[grp][1]);
                split2(S[grp][2 * ks + 1][0], S[grp][2 * ks + 1][1], ah[grp][2], al[grp][2]);
                split2(S[grp][2 * ks + 1][2], S[grp][2 * ks + 1][3], ah[grp][3], al[grp][3]);
            }
#pragma unroll
            for (int p = 0; p < 4; p++) {
                uint32_t off = (uint32_t)((p * 576 + ks * 8) * 4) + lwB;
                uint32_t h0, h1, h2, h3, l0, l1, l2, l3;
                ldsm4(h0, h1, h2, h3, vaddr + off);
                ldsm4(l0, l1, l2, l3, vaddrL + off);
#pragma unroll
                for (int grp = 0; grp < 2; grp++) {
                    mma16816(O[grp][2 * p],     ah[grp][0], ah[grp][1], ah[grp][2], ah[grp][3], h0, h1);
                    mma16816(O[grp][2 * p],     ah[grp][0], ah[grp][1], ah[grp][2], ah[grp][3], l0, l1);
                    mma16816(O[grp][2 * p],     al[grp][0], al[grp][1], al[grp][2], al[grp][3], h0, h1);
                    mma16816(O[grp][2 * p + 1], ah[grp][0], ah[grp][1], ah[grp][2], ah[grp][3], h2, h3);
                    mma16816(O[grp][2 * p + 1], ah[grp][0], ah[grp][1], ah[grp][2], ah[grp][3], l2, l3);
                    mma16816(O[grp][2 * p + 1], al[grp][0], al[grp][1], al[grp][2], al[grp][3], h2, h3);
                }
            }
        }
    }

    // ---- epilogue
#pragma unroll
    for (int grp = 0; grp < 2; grp++) {
        float inv0 = 1.0f / l0s[grp], inv1 = 1.0f / l1s[grp];
        const size_t r0 = (size_t)(bm * 128 + wid * 32 + grp * 16 + g);
#pragma unroll
        for (int nt = 0; nt < 8; nt++) {
            int w = h * 32 + nt * 4 + q;
            uint32_t H, L;
            split2(O[grp][nt][0] * inv0, O[grp][nt][1] * inv0, H, L);
            g_HH[r0 * 256 + w] = H;
            g_HL[r0 * 256 + w] = L;
            split2(O[grp][nt][2] * inv1, O[grp][nt][3] * inv1, H, L);
            g_HH[(r0 + 8) * 256 + w] = H;
            g_HL[(r0 + 8) * 256 + w] = L;
        }
    }
}

// ---------------- launcher --------------------------------------------------
extern "C" void kernel_launch(void* const* d_in, const int* in_sizes, int n_in,
                              void* d_out, int out_size) {
    const float* X   = (const float*)d_in[0];
    const int*   msk = (const int*)d_in[1];
    const float* WQ  = (const float*)d_in[2];
    const float* WK  = (const float*)d_in[3];
    const float* WV  = (const float*)d_in[4];
    const float* WO  = (const float*)d_in[5];
    float* out = (float*)d_out;

    cudaFuncSetAttribute(attn_kernel, cudaFuncAttributeMaxDynamicSharedMemorySize,
                         ATTN_SMEM_BYTES);
    cudaFuncSetAttribute(qkv_fused, cudaFuncAttributeMaxDynamicSharedMemorySize,
                         QKV_SMEM_WORDS * 4);

    split_kernel<<<256, 256>>>(WQ, 1, HNUM * HD * FIN / 4);
    split_kernel<<<256, 256>>>(WK, 2, HNUM * HD * FIN / 4);
    split_kernel<<<256, 256>>>(WV, 3, HNUM * HD * FIN / 4);
    split_kernel<<<256, 256>>>(WO, 4, FIN * FIN / 4);

    qkv_fused<<<dim3(NSEQ / 64, HNUM), 128, QKV_SMEM_WORDS * 4>>>(X);
    attn_kernel<<<dim3(NSEQ / 128, HNUM), 128, ATTN_SMEM_BYTES>>>(msk);
    out_kernel<<<dim3(NSEQ / 128, FIN / HD), 256>>>(out);
}

// round 7
// speedup vs baseline: 1.0587x; 1.0587x over previous
#include <cuda_runtime.h>
#include <cuda_bf16.h>
#include <cstdint>

#define HNUM 8
#define NSEQ 4096
#define FIN  512
#define HD   64

// ---------------- scratch (static device globals; no allocations) ----------
__device__ uint32_t g_WH[3 * HNUM * HD * (FIN / 2)];
__device__ uint32_t g_WL[3 * HNUM * HD * (FIN / 2)];
__device__ uint32_t g_WOH[FIN * (FIN / 2)];
__device__ uint32_t g_WOL[FIN * (FIN / 2)];
__device__ uint32_t g_QH[HNUM * NSEQ * (HD / 2)];
__device__ uint32_t g_QL[HNUM * NSEQ * (HD / 2)];
__device__ uint32_t g_KH[HNUM * NSEQ * (HD / 2)];
__device__ uint32_t g_KL[HNUM * NSEQ * (HD / 2)];
__device__ unsigned short g_VTH[HNUM * HD * NSEQ];
__device__ unsigned short g_VTL[HNUM * HD * NSEQ];
__device__ uint32_t g_HH[NSEQ * (FIN / 2)];
__device__ uint32_t g_HL[NSEQ * (FIN / 2)];

// ---------------- helpers --------------------------------------------------
__device__ __forceinline__ uint32_t pack_bf16x2(float lo_elem, float hi_elem) {
    return (uint32_t)__bfloat16_as_ushort(__float2bfloat16_rn(lo_elem)) |
           ((uint32_t)__bfloat16_as_ushort(__float2bfloat16_rn(hi_elem)) << 16);
}

__device__ __forceinline__ void split2(float a, float b, uint32_t& hi, uint32_t& lo) {
    float ah = __bfloat162float(__float2bfloat16_rn(a));
    float bh = __bfloat162float(__float2bfloat16_rn(b));
    hi = pack_bf16x2(a, b);
    lo = pack_bf16x2(a - ah, b - bh);
}

__device__ __forceinline__ void mma16816(float* c,
                                         uint32_t a0, uint32_t a1, uint32_t a2, uint32_t a3,
                                         uint32_t b0, uint32_t b1) {
    asm volatile(
        "mma.sync.aligned.m16n8k16.row.col.f32.bf16.bf16.f32 "
        "{%0,%1,%2,%3},{%4,%5,%6,%7},{%8,%9},{%0,%1,%2,%3};\n"
        : "+f"(c[0]), "+f"(c[1]), "+f"(c[2]), "+f"(c[3])
        : "r"(a0), "r"(a1), "r"(a2), "r"(a3), "r"(b0), "r"(b1));
}

__device__ __forceinline__ void ldsm4(uint32_t& r0, uint32_t& r1, uint32_t& r2,
                                      uint32_t& r3, uint32_t addr) {
    asm volatile("ldmatrix.sync.aligned.m8n8.x4.shared.b16 {%0,%1,%2,%3},[%4];"
                 : "=r"(r0), "=r"(r1), "=r"(r2), "=r"(r3) : "r"(addr));
}

__device__ __forceinline__ void cp16(uint32_t dst, const void* src) {
    asm volatile("cp.async.cg.shared.global [%0], [%1], 16;" :: "r"(dst), "l"(src));
}
__device__ __forceinline__ void cp_commit() {
    asm volatile("cp.async.commit_group;" ::: "memory");
}
__device__ __forceinline__ void cp_wait1() {
    asm volatile("cp.async.wait_group 1;" ::: "memory");
}
__device__ __forceinline__ void cp_wait0() {
    asm volatile("cp.async.wait_group 0;" ::: "memory");
}
__device__ __forceinline__ void prefetchL2(const void* p) {
    asm volatile("prefetch.global.L2 [%0];" :: "l"(p));
}

#define NEG_BIG (-1.0e30f)
#define SCALE2  0.18033688f   /* 0.125 * log2(e) */

// ---------------- merged split kernel: 4 weight tensors, 65536 quads each ---
__global__ void __launch_bounds__(256) split_all(const float* __restrict__ wq,
                                                 const float* __restrict__ wk,
                                                 const float* __restrict__ wv,
                                                 const float* __restrict__ wo) {
    const int which = blockIdx.y;
    const float* src;
    uint32_t* dH;
    uint32_t* dL;
    switch (which) {
        case 0: src = wq; dH = g_WH;          dL = g_WL;          break;
        case 1: src = wk; dH = g_WH + 131072; dL = g_WL + 131072; break;
        case 2: src = wv; dH = g_WH + 262144; dL = g_WL + 262144; break;
        default: src = wo; dH = g_WOH;        dL = g_WOL;         break;
    }
    const int nquads = 65536;
    for (int i = blockIdx.x * blockDim.x + threadIdx.x; i < nquads;
         i += gridDim.x * blockDim.x) {
        float4 v = reinterpret_cast<const float4*>(src)[i];
        uint32_t h0, l0, h1, l1;
        split2(v.x, v.y, h0, l0);
        split2(v.z, v.w, h1, l1);
        reinterpret_cast<uint2*>(dH)[i] = make_uint2(h0, h1);
        reinterpret_cast<uint2*>(dL)[i] = make_uint2(l0, l1);
    }
}

// ---------------- stage 1: fused QKV projection -----------------------------
#define QKV_SMEM_WORDS 18432

__global__ void __launch_bounds__(128, 3) qkv_fused(const float* __restrict__ X) {
    extern __shared__ __align__(16) uint32_t qs[];
    const uint32_t sbase = (uint32_t)__cvta_generic_to_shared(qs);
    const int tid = threadIdx.x, wid = tid >> 5, lane = tid & 31;
    const int g = lane >> 2, q = lane & 3;
    const int bm = blockIdx.x, h = blockIdx.y;

    const int jm = lane >> 3, im = lane & 7;
    const uint32_t lwB = (uint32_t)(((8 * (jm >> 1) + im) * 36 + (jm & 1) * 4) * 4);
    const uint32_t lwA = (uint32_t)(((lane & 15) * 36 + (lane >> 4) * 4) * 4);

    float acc[3][8][4];
#pragma unroll
    for (int z = 0; z < 3; z++)
#pragma unroll
        for (int i = 0; i < 8; i++)
#pragma unroll
            for (int j = 0; j < 4; j++) acc[z][i][j] = 0.f;

    const float* Xbase = X + ((size_t)h * NSEQ + (size_t)bm * 64) * FIN;

    for (int kc = 0; kc < 8; kc++) {
#pragma unroll
        for (int j = 0; j < 8; j++) {
            int idx = tid + j * 128;
            int r = idx >> 4, c4 = (idx & 15) << 2;
            float4 v = *reinterpret_cast<const float4*>(Xbase + (size_t)r * FIN + kc * 64 + c4);
            uint32_t h0, l0, h1, l1;
            split2(v.x, v.y, h0, l0);
            split2(v.z, v.w, h1, l1);
            *reinterpret_cast<uint2*>(&qs[r * 36 + (c4 >> 1)]) = make_uint2(h0, h1);
            *reinterpret_cast<uint2*>(&qs[2304 + r * 36 + (c4 >> 1)]) = make_uint2(l0, l1);
        }
#pragma unroll
        for (int z = 0; z < 3; z++) {
            const uint32_t* BH = g_WH + ((size_t)(z * HNUM + h) * HD) * 256 + kc * 32;
            const uint32_t* BL = g_WL + ((size_t)(z * HNUM + h) * HD) * 256 + kc * 32;
#pragma unroll
            for (int j = 0; j < 4; j++) {
                int idx = tid + j * 128;
                int r = idx >> 3, c = (idx & 7) << 2;
                *reinterpret_cast<uint4*>(&qs[4608 + z * 2304 + r * 36 + c]) =
                    *reinterpret_cast<const uint4*>(BH + (size_t)r * 256 + c);
                *reinterpret_cast<uint4*>(&qs[11520 + z * 2304 + r * 36 + c]) =
                    *reinterpret_cast<const uint4*>(BL + (size_t)r * 256 + c);
            }
        }
        __syncthreads();
#pragma unroll
        for (int ks = 0; ks < 4; ks++) {
            uint32_t a0h, a1h, a2h, a3h, a0l, a1l, a2l, a3l;
            uint32_t aoff = sbase + (uint32_t)((wid * 16 * 36 + ks * 8) * 4) + lwA;
            ldsm4(a0h, a1h, a2h, a3h, aoff);
            ldsm4(a0l, a1l, a2l, a3l, aoff + 2304 * 4);
#pragma unroll
            for (int z = 0; z < 3; z++) {
                uint32_t bbase = sbase + (uint32_t)((4608 + z * 2304) * 4);
#pragma unroll
                for (int p = 0; p < 4; p++) {
                    uint32_t off = bbase + (uint32_t)((p * 576 + ks * 8) * 4) + lwB;
                    uint32_t b0, b1, b2, b3, c0, c1, c2, c3;
                    ldsm4(b0, b1, b2, b3, off);
                    ldsm4(c0, c1, c2, c3, off + 6912 * 4);
                    mma16816(acc[z][2 * p],     a0h, a1h, a2h, a3h, b0, b1);
                    mma16816(acc[z][2 * p],     a0h, a1h, a2h, a3h, c0, c1);
                    mma16816(acc[z][2 * p],     a0l, a1l, a2l, a3l, b0, b1);
                    mma16816(acc[z][2 * p + 1], a0h, a1h, a2h, a3h, b2, b3);
                    mma16816(acc[z][2 * p + 1], a0h, a1h, a2h, a3h, c2, c3);
                    mma16816(acc[z][2 * p + 1], a0l, a1l, a2l, a3l, b2, b3);
                }
            }
        }
        __syncthreads();
    }

    const int r0 = wid * 16 + g;
#pragma unroll
    for (int z = 0; z < 2; z++) {
        uint32_t* dH = (z == 0) ? g_QH : g_KH;
        uint32_t* dL = (z == 0) ? g_QL : g_KL;
        const size_t rb0 = (size_t)(h * NSEQ + bm * 64 + r0) * 32;
        const size_t rb1 = rb0 + 8 * 32;
#pragma unroll
        for (int nt = 0; nt < 8; nt++) {
            int w = nt * 4 + q;
            uint32_t H, L;
            split2(acc[z][nt][0], acc[z][nt][1], H, L);
            dH[rb0 + w] = H; dL[rb0 + w] = L;
            split2(acc[z][nt][2], acc[z][nt][3], H, L);
            dH[rb1 + w] = H; dL[rb1 + w] = L;
        }
    }
    {
        const int n0 = bm * 64 + r0;
#pragma unroll
        for (int nt = 0; nt < 8; nt++) {
            int cx = nt * 8 + 2 * q;
#pragma unroll
            for (int e = 0; e < 2; e++) {
                size_t b0 = (size_t)(h * HD + cx + e) * NSEQ;
                float v0 = acc[2][nt][e], v1 = acc[2][nt][2 + e];
                float h0 = __bfloat162float(__float2bfloat16_rn(v0));
                float h1 = __bfloat162float(__float2bfloat16_rn(v1));
                g_VTH[b0 + n0]     = __bfloat16_as_ushort(__float2bfloat16_rn(v0));
                g_VTL[b0 + n0]     = __bfloat16_as_ushort(__float2bfloat16_rn(v0 - h0));
                g_VTH[b0 + n0 + 8] = __bfloat16_as_ushort(__float2bfloat16_rn(v1));
                g_VTL[b0 + n0 + 8] = __bfloat16_as_ushort(__float2bfloat16_rn(v1 - h1));
            }
        }
    }
}

// ---------------- stage 3: output projection ------------------------------
__device__ __forceinline__ void gemm_accum(const uint32_t* __restrict__ AHg,
                                           const uint32_t* __restrict__ ALg,
                                           const uint32_t* __restrict__ BHg,
                                           const uint32_t* __restrict__ BLg,
                                           float acc[8][4]) {
    __shared__ __align__(16) uint32_t AsH[128][36];
    __shared__ __align__(16) uint32_t AsL[128][36];
    __shared__ __align__(16) uint32_t BsH[64][36];
    __shared__ __align__(16) uint32_t BsL[64][36];

    const int tid = threadIdx.x;
    const int wid = tid >> 5, lane = tid & 31;
    const int g = lane >> 2, q = lane & 3;

    for (int kc = 0; kc < 256; kc += 32) {
#pragma unroll
        for (int j = 0; j < 4; j++) {
            int idx = tid + j * 256;
            int r = idx >> 3, c = (idx & 7) << 2;
            *reinterpret_cast<uint4*>(&AsH[r][c]) =
                *reinterpret_cast<const uint4*>(AHg + (size_t)r * 256 + kc + c);
            *reinterpret_cast<uint4*>(&AsL[r][c]) =
                *reinterpret_cast<const uint4*>(ALg + (size_t)r * 256 + kc + c);
        }
#pragma unroll
        for (int j = 0; j < 2; j++) {
            int idx = tid + j * 256;
            int r = idx >> 3, c = (idx & 7) << 2;
            *reinterpret_cast<uint4*>(&BsH[r][c]) =
                *reinterpret_cast<const uint4*>(BHg + (size_t)r * 256 + kc + c);
            *reinterpret_cast<uint4*>(&BsL[r][c]) =
                *reinterpret_cast<const uint4*>(BLg + (size_t)r * 256 + kc + c);
        }
        __syncthreads();
#pragma unroll
        for (int ks = 0; ks < 4; ks++) {
            const int ar = wid * 16 + g;
            const int wi = ks * 8 + q;
            uint32_t a0h = AsH[ar][wi],     a1h = AsH[ar + 8][wi];
            uint32_t a2h = AsH[ar][wi + 4], a3h = AsH[ar + 8][wi + 4];
            uint32_t a0l = AsL[ar][wi],     a1l = AsL[ar + 8][wi];
            uint32_t a2l = AsL[ar][wi + 4], a3l = AsL[ar + 8][wi + 4];
#pragma unroll
            for (int nt = 0; nt < 8; nt++) {
                const int br = nt * 8 + g;
                uint32_t b0h = BsH[br][wi], b1h = BsH[br][wi + 4];
                uint32_t b0l = BsL[br][wi], b1l = BsL[br][wi + 4];
                mma16816(acc[nt], a0h, a1h, a2h, a3h, b0h, b1h);
                mma16816(acc[nt], a0h, a1h, a2h, a3h, b0l, b1l);
                mma16816(acc[nt], a0l, a1l, a2l, a3l, b0h, b1h);
            }
        }
        __syncthreads();
    }
}

__global__ void __launch_bounds__(256) out_kernel(float* __restrict__ out) {
    const int bm = blockIdx.x, bn = blockIdx.y;
    const int tid = threadIdx.x;
    const int wid = tid >> 5, lane = tid & 31;
    const int g = lane >> 2, q = lane & 3;

    float acc[8][4];
#pragma unroll
    for (int i = 0; i < 8; i++)
#pragma unroll
        for (int j = 0; j < 4; j++) acc[i][j] = 0.f;

    gemm_accum(g_HH + (size_t)bm * 128 * 256, g_HL + (size_t)bm * 128 * 256,
               g_WOH + (size_t)bn * HD * 256, g_WOL + (size_t)bn * HD * 256, acc);

    const int r0 = wid * 16 + g;
#pragma unroll
    for (int nt = 0; nt < 8; nt++) {
        int cx = bn * HD + nt * 8 + 2 * q;
        *reinterpret_cast<float2*>(out + (size_t)(bm * 128 + r0) * FIN + cx) =
            make_float2(acc[nt][0], acc[nt][1]);
        *reinterpret_cast<float2*>(out + (size_t)(bm * 128 + r0 + 8) * FIN + cx) =
            make_float2(acc[nt][2], acc[nt][3]);
    }
}

// ---------------- stage 2: flash attention (BM=128, 256 threads, 16 rows/warp)
#define ATTN_BUF_WORDS 9216
#define ATTN_SMEM_BYTES (2 * ATTN_BUF_WORDS * 4)

__device__ __forceinline__ void issue_tile(int h, int nb, uint32_t sbase) {
    const int tid = threadIdx.x;
#pragma unroll
    for (int j = 0; j < 2; j++) {
        int chunk = tid + j * 256;
        int r = chunk >> 3, c = chunk & 7;
        const uint32_t* sKH = g_KH + (size_t)(h * NSEQ + nb * 64 + r) * 32 + c * 4;
        const uint32_t* sKL = g_KL + (size_t)(h * NSEQ + nb * 64 + r) * 32 + c * 4;
        const unsigned short* sVH = g_VTH + (size_t)(h * HD + r) * NSEQ + nb * 64 + c * 8;
        const unsigned short* sVL = g_VTL + (size_t)(h * HD + r) * NSEQ + nb * 64 + c * 8;
        uint32_t off = (uint32_t)(r * 36 + c * 4) * 4;
        cp16(sbase + off, sKH);
        cp16(sbase + off + 2304 * 4, sKL);
        cp16(sbase + off + 4608 * 4, sVH);
        cp16(sbase + off + 6912 * 4, sVL);
    }
}

__global__ void __launch_bounds__(256) attn_kernel(const int* __restrict__ mask) {
    extern __shared__ __align__(16) uint32_t sm[];
    const uint32_t smem_u32 = (uint32_t)__cvta_generic_to_shared(sm);

    const int tid = threadIdx.x, wid = tid >> 5, lane = tid & 31;
    const int g = lane >> 2, q = lane & 3;
    const int bm = blockIdx.x, h = blockIdx.y;

    const int jm = lane >> 3, im = lane & 7;
    const uint32_t lwB = (uint32_t)(((8 * (jm >> 1) + im) * 36 + (jm & 1) * 4) * 4);

    uint32_t qh[4][4], ql[4][4];
    {
        const size_t rb0 = (size_t)(h * NSEQ + bm * 128 + wid * 16 + g) * 32;
        const size_t rb1 = rb0 + 8 * 32;
#pragma unroll
        for (int ks = 0; ks < 4; ks++) {
            int wi = ks * 8 + q;
            qh[ks][0] = g_QH[rb0 + wi];
            qh[ks][1] = g_QH[rb1 + wi];
            qh[ks][2] = g_QH[rb0 + wi + 4];
            qh[ks][3] = g_QH[rb1 + wi + 4];
            ql[ks][0] = g_QL[rb0 + wi];
            ql[ks][1] = g_QL[rb1 + wi];
            ql[ks][2] = g_QL[rb0 + wi + 4];
            ql[ks][3] = g_QL[rb1 + wi + 4];
        }
    }

    const int* mr0 = mask + ((size_t)h * NSEQ + (size_t)(bm * 128 + wid * 16 + g)) * NSEQ;
    const int* mr1 = mr0 + 8 * NSEQ;

    float O[8][4];
#pragma unroll
    for (int i = 0; i < 8; i++)
#pragma unroll
        for (int j = 0; j < 4; j++) O[i][j] = 0.f;
    const float NEGINF = __int_as_float(0xff800000);
    float m0 = NEGINF, m1 = NEGINF, l0s = 0.f, l1s = 0.f;

    prefetchL2(mr0);
    prefetchL2(mr0 + 32);
    prefetchL2(mr1);
    prefetchL2(mr1 + 32);

    issue_tile(h, 0, smem_u32);
    cp_commit();

    for (int nb = 0; nb < NSEQ / 64; nb++) {
        if (nb + 1 < NSEQ / 64) {
            const int* p0 = mr0 + (nb + 1) * 64;
            const int* p1 = mr1 + (nb + 1) * 64;
            prefetchL2(p0);
            prefetchL2(p0 + 32);
            prefetchL2(p1);
            prefetchL2(p1 + 32);
        }

        __syncthreads();
        if (nb + 1 < NSEQ / 64) {
            issue_tile(h, nb + 1, smem_u32 + ((nb + 1) & 1) * ATTN_BUF_WORDS * 4);
            cp_commit();
            cp_wait1();
        } else {
            cp_wait0();
        }
        __syncthreads();

        const uint32_t kaddr  = smem_u32 + (uint32_t)((nb & 1) * ATTN_BUF_WORDS) * 4;
        const uint32_t kaddrL = kaddr + 2304 * 4;
        const uint32_t vaddr  = kaddr + 4608 * 4;
        const uint32_t vaddrL = kaddr + 6912 * 4;

        // ---- S = Q * K^T
        float S[8][4];
#pragma unroll
        for (int i = 0; i < 8; i++)
#pragma unroll
            for (int j = 0; j < 4; j++) S[i][j] = 0.f;
#pragma unroll
        for (int ks = 0; ks < 4; ks++) {
#pragma unroll
            for (int p = 0; p < 4; p++) {
                uint32_t off = (uint32_t)((p * 576 + ks * 8) * 4) + lwB;
                uint32_t h0, h1, h2, h3, l0, l1, l2, l3;
                ldsm4(h0, h1, h2, h3, kaddr + off);
                ldsm4(l0, l1, l2, l3, kaddrL + off);
                mma16816(S[2 * p],     qh[ks][0], qh[ks][1], qh[ks][2], qh[ks][3], h0, h1);
                mma16816(S[2 * p],     qh[ks][0], qh[ks][1], qh[ks][2], qh[ks][3], l0, l1);
                mma16816(S[2 * p],     ql[ks][0], ql[ks][1], ql[ks][2], ql[ks][3], h0, h1);
                mma16816(S[2 * p + 1], qh[ks][0], qh[ks][1], qh[ks][2], qh[ks][3], h2, h3);
                mma16816(S[2 * p + 1], qh[ks][0], qh[ks][1], qh[ks][2], qh[ks][3], l2, l3);
                mma16816(S[2 * p + 1], ql[ks][0], ql[ks][1], ql[ks][2], ql[ks][3], h2, h3);
            }
        }

        // ---- mask + fold (0.125*log2e)
#pragma unroll
        for (int nt = 0; nt < 8; nt++) {
            int2 ma = *reinterpret_cast<const int2*>(mr0 + nb * 64 + nt * 8 + 2 * q);
            int2 mb = *reinterpret_cast<const int2*>(mr1 + nb * 64 + nt * 8 + 2 * q);
            S[nt][0] = ma.x ? S[nt][0] * SCALE2 : NEG_BIG;
            S[nt][1] = ma.y ? S[nt][1] * SCALE2 : NEG_BIG;
            S[nt][2] = mb.x ? S[nt][2] * SCALE2 : NEG_BIG;
            S[nt][3] = mb.y ? S[nt][3] * SCALE2 : NEG_BIG;
        }

        // ---- online softmax (log2 domain)
        float mx0 = S[0][0], mx1 = S[0][2];
#pragma unroll
        for (int nt = 0; nt < 8; nt++) {
            mx0 = fmaxf(mx0, fmaxf(S[nt][0], S[nt][1]));
            mx1 = fmaxf(mx1, fmaxf(S[nt][2], S[nt][3]));
        }
        mx0 = fmaxf(mx0, __shfl_xor_sync(0xffffffffu, mx0, 1));
        mx0 = fmaxf(mx0, __shfl_xor_sync(0xffffffffu, mx0, 2));
        mx1 = fmaxf(mx1, __shfl_xor_sync(0xffffffffu, mx1, 1));
        mx1 = fmaxf(mx1, __shfl_xor_sync(0xffffffffu, mx1, 2));

        float mn0 = fmaxf(m0, mx0), mn1 = fmaxf(m1, mx1);
        float al0 = exp2f(m0 - mn0), al1 = exp2f(m1 - mn1);
        m0 = mn0;
        m1 = mn1;

        float rs0 = 0.f, rs1 = 0.f;
#pragma unroll
        for (int nt = 0; nt < 8; nt++) {
            S[nt][0] = exp2f(S[nt][0] - m0);
            S[nt][1] = exp2f(S[nt][1] - m0);
            S[nt][2] = exp2f(S[nt][2] - m1);
            S[nt][3] = exp2f(S[nt][3] - m1);
            rs0 += S[nt][0] + S[nt][1];
            rs1 += S[nt][2] + S[nt][3];
        }
        rs0 += __shfl_xor_sync(0xffffffffu, rs0, 1);
        rs0 += __shfl_xor_sync(0xffffffffu, rs0, 2);
        rs1 += __shfl_xor_sync(0xffffffffu, rs1, 1);
        rs1 += __shfl_xor_sync(0xffffffffu, rs1, 2);
        l0s = l0s * al0 + rs0;
        l1s = l1s * al1 + rs1;
#pragma unroll
        for (int nt = 0; nt < 8; nt++) {
            O[nt][0] *= al0;
            O[nt][1] *= al0;
            O[nt][2] *= al1;
            O[nt][3] *= al1;
        }

        // ---- O += P * V
#pragma unroll
        for (int ks = 0; ks < 4; ks++) {
            uint32_t a0h, a0l, a1h, a1l, a2h, a2l, a3h, a3l;
            split2(S[2 * ks][0],     S[2 * ks][1],     a0h, a0l);
            split2(S[2 * ks][2],     S[2 * ks][3],     a1h, a1l);
            split2(S[2 * ks + 1][0], S[2 * ks + 1][1], a2h, a2l);
            split2(S[2 * ks + 1][2], S[2 * ks + 1][3], a3h, a3l);
#pragma unroll
            for (int p = 0; p < 4; p++) {
                uint32_t off = (uint32_t)((p * 576 + ks * 8) * 4) + lwB;
                uint32_t h0, h1, h2, h3, l0, l1, l2, l3;
                ldsm4(h0, h1, h2, h3, vaddr + off);
                ldsm4(l0, l1, l2, l3, vaddrL + off);
                mma16816(O[2 * p],     a0h, a1h, a2h, a3h, h0, h1);
                mma16816(O[2 * p],     a0h, a1h, a2h, a3h, l0, l1);
                mma16816(O[2 * p],     a0l, a1l, a2l, a3l, h0, h1);
                mma16816(O[2 * p + 1], a0h, a1h, a2h, a3h, h2, h3);
                mma16816(O[2 * p + 1], a0h, a1h, a2h, a3h, l2, l3);
                mma16816(O[2 * p + 1], a0l, a1l, a2l, a3l, h2, h3);
            }
        }
    }

    // ---- epilogue
    float inv0 = 1.0f / l0s, inv1 = 1.0f / l1s;
    const size_t r0 = (size_t)(bm * 128 + wid * 16 + g);
#pragma unroll
    for (int nt = 0; nt < 8; nt++) {
        int w = h * 32 + nt * 4 + q;
        uint32_t H, L;
        split2(O[nt][0] * inv0, O[nt][1] * inv0, H, L);
        g_HH[r0 * 256 + w] = H;
        g_HL[r0 * 256 + w] = L;
        split2(O[nt][2] * inv1, O[nt][3] * inv1, H, L);
        g_HH[(r0 + 8) * 256 + w] = H;
        g_HL[(r0 + 8) * 256 + w] = L;
    }
}

// ---------------- launcher --------------------------------------------------
extern "C" void kernel_launch(void* const* d_in, const int* in_sizes, int n_in,
                              void* d_out, int out_size) {
    const float* X   = (const float*)d_in[0];
    const int*   msk = (const int*)d_in[1];
    const float* WQ  = (const float*)d_in[2];
    const float* WK  = (const float*)d_in[3];
    const float* WV  = (const float*)d_in[4];
    const float* WO  = (const float*)d_in[5];
    float* out = (float*)d_out;

    cudaFuncSetAttribute(attn_kernel, cudaFuncAttributeMaxDynamicSharedMemorySize,
                         ATTN_SMEM_BYTES);
    cudaFuncSetAttribute(qkv_fused, cudaFuncAttributeMaxDynamicSharedMemorySize,
                         QKV_SMEM_WORDS * 4);

    split_all<<<dim3(256, 4), 256>>>(WQ, WK, WV, WO);

    qkv_fused<<<dim3(NSEQ / 64, HNUM), 128, QKV_SMEM_WORDS * 4>>>(X);
    attn_kernel<<<dim3(NSEQ / 128, HNUM), 256, ATTN_SMEM_BYTES>>>(msk);
    out_kernel<<<dim3(NSEQ / 128, FIN / HD), 256>>>(out);
}